// round 6
// baseline (speedup 1.0000x reference)
#include <cuda_runtime.h>
#include <cuda_bf16.h>
#include <math.h>

// ---------------------------------------------------------------------------
// Problem constants
// ---------------------------------------------------------------------------
#define TSEQ 2048
#define HD   512        // hidden size H
#define EMB  512        // embedding dim E
#define G4H  2048       // 4*H
#define NTAGS 12
#define START_TAG 10
#define STOP_TAG  11
#define NEGV (-10000.0f)

// ---------------------------------------------------------------------------
// Scratch (device globals; no allocations allowed)
// ---------------------------------------------------------------------------
__device__ float g_x0[TSEQ * EMB];                 // embedded input      4 MB
__device__ float g_G[2 * TSEQ * G4H];              // input projections  32 MB (reused per layer)
__device__ float g_hcat0[TSEQ * 2 * HD];           // layer0 output       8 MB
__device__ float g_hcat1[TSEQ * 2 * HD];           // layer1 output       8 MB
__device__ float g_feats[TSEQ * NTAGS];
__device__ unsigned long long g_hstamp[2 * 2 * HD]; // [dir][parity][H] stamped h

// ---------------------------------------------------------------------------
// Helpers
// ---------------------------------------------------------------------------
__device__ __forceinline__ unsigned long long ld_relaxed_u64(const unsigned long long* p) {
    unsigned long long v;
    asm volatile("ld.relaxed.gpu.global.b64 %0, [%1];" : "=l"(v) : "l"(p) : "memory");
    return v;
}
__device__ __forceinline__ void st_relaxed_u64(unsigned long long* p, unsigned long long v) {
    asm volatile("st.relaxed.gpu.global.b64 [%0], %1;" :: "l"(p), "l"(v) : "memory");
}

// packed f32x2 FMA (FFMA2 — only reachable via PTX)
__device__ __forceinline__ unsigned long long ffma2(unsigned long long a,
                                                    unsigned long long b,
                                                    unsigned long long c) {
    unsigned long long d;
    asm("fma.rn.f32x2 %0, %1, %2, %3;" : "=l"(d) : "l"(a), "l"(b), "l"(c));
    return d;
}
__device__ __forceinline__ unsigned long long pack2(float x, float y) {
    unsigned long long d;
    asm("mov.b64 %0, {%1, %2};" : "=l"(d) : "f"(x), "f"(y));
    return d;
}
__device__ __forceinline__ float2 unpack2(unsigned long long v) {
    float2 r;
    asm("mov.b64 {%0, %1}, %2;" : "=f"(r.x), "=f"(r.y) : "l"(v));
    return r;
}

// HW tanh (MUFU-class, ~1e-5 abs err) and sigmoid via tanh
__device__ __forceinline__ float tanh_hw(float x) {
    float y;
    asm("tanh.approx.f32 %0, %1;" : "=f"(y) : "f"(x));
    return y;
}
__device__ __forceinline__ float sig_hw(float x) {
    return fmaf(0.5f, tanh_hw(0.5f * x), 0.5f);
}

// ---------------------------------------------------------------------------
// 0) reset stamp buffers (must run before each scan launch)
// ---------------------------------------------------------------------------
__global__ void init_stamps_kernel() {
    int i = blockIdx.x * blockDim.x + threadIdx.x;
    if (i < 2 * 2 * HD) g_hstamp[i] = 0ULL;
}

// ---------------------------------------------------------------------------
// 1) embedding gather: x0[t][e] = emb[sentence[t]][e]
// ---------------------------------------------------------------------------
__global__ void embed_kernel(const int* __restrict__ sentence,
                             const float* __restrict__ emb) {
    int t = blockIdx.x;
    int v = sentence[t];
    const float4* src = (const float4*)(emb + (size_t)v * EMB);
    float4* dst = (float4*)(g_x0 + (size_t)t * EMB);
    dst[threadIdx.x] = src[threadIdx.x];   // 128 threads * float4 = 512 floats
}

// ---------------------------------------------------------------------------
// 2) input-projection GEMM with packed f32x2 FMAs
//    C[d][t][r] = sum_k A[t][k]*W[d][r][k] + b1[d][r]+b2[d][r]
//    128x128 tile, BK=16, 256 threads, 8x8 per thread (acc packed as 8x4 u64)
// ---------------------------------------------------------------------------
#define BM 128
#define BN 128
#define BK 16

__global__ void __launch_bounds__(256)
gemm_bias_kernel(const float* __restrict__ W,
                 const float* __restrict__ b1,
                 const float* __restrict__ b2,
                 int K, int layer) {
    const float* A = layer ? g_hcat0 : g_x0;
    __shared__ __align__(16) float As[BK][BM + 4];
    __shared__ __align__(16) float Bs[BK][BN + 4];

    int dir = blockIdx.z;
    const float* Wd = W + (size_t)dir * G4H * K;
    float* Cd = g_G + (size_t)dir * TSEQ * G4H;

    int tid = threadIdx.x;
    int tx = tid % 16, ty = tid / 16;
    int m0 = blockIdx.y * BM, n0 = blockIdx.x * BN;

    unsigned long long acc2[8][4];
#pragma unroll
    for (int i = 0; i < 8; i++)
#pragma unroll
        for (int j = 0; j < 4; j++) acc2[i][j] = 0ULL;

    int lr = tid >> 1;            // 0..127
    int lc = (tid & 1) * 8;       // 0 or 8

    for (int k0 = 0; k0 < K; k0 += BK) {
        float4 a0 = *(const float4*)(A  + (size_t)(m0 + lr) * K + k0 + lc);
        float4 a1 = *(const float4*)(A  + (size_t)(m0 + lr) * K + k0 + lc + 4);
        float4 w0 = *(const float4*)(Wd + (size_t)(n0 + lr) * K + k0 + lc);
        float4 w1 = *(const float4*)(Wd + (size_t)(n0 + lr) * K + k0 + lc + 4);
        __syncthreads();
        As[lc + 0][lr] = a0.x; As[lc + 1][lr] = a0.y; As[lc + 2][lr] = a0.z; As[lc + 3][lr] = a0.w;
        As[lc + 4][lr] = a1.x; As[lc + 5][lr] = a1.y; As[lc + 6][lr] = a1.z; As[lc + 7][lr] = a1.w;
        Bs[lc + 0][lr] = w0.x; Bs[lc + 1][lr] = w0.y; Bs[lc + 2][lr] = w0.z; Bs[lc + 3][lr] = w0.w;
        Bs[lc + 4][lr] = w1.x; Bs[lc + 5][lr] = w1.y; Bs[lc + 6][lr] = w1.z; Bs[lc + 7][lr] = w1.w;
        __syncthreads();
#pragma unroll
        for (int kk = 0; kk < BK; kk++) {
            float4 t0 = *(const float4*)&As[kk][ty * 8];
            float4 t1 = *(const float4*)&As[kk][ty * 8 + 4];
            unsigned long long ad[8];
            ad[0] = pack2(t0.x, t0.x); ad[1] = pack2(t0.y, t0.y);
            ad[2] = pack2(t0.z, t0.z); ad[3] = pack2(t0.w, t0.w);
            ad[4] = pack2(t1.x, t1.x); ad[5] = pack2(t1.y, t1.y);
            ad[6] = pack2(t1.z, t1.z); ad[7] = pack2(t1.w, t1.w);
            const ulonglong2* bp2 = (const ulonglong2*)&Bs[kk][tx * 8];
            ulonglong2 b01 = bp2[0];
            ulonglong2 b23 = bp2[1];
#pragma unroll
            for (int i = 0; i < 8; i++) {
                acc2[i][0] = ffma2(ad[i], b01.x, acc2[i][0]);
                acc2[i][1] = ffma2(ad[i], b01.y, acc2[i][1]);
                acc2[i][2] = ffma2(ad[i], b23.x, acc2[i][2]);
                acc2[i][3] = ffma2(ad[i], b23.y, acc2[i][3]);
            }
        }
    }

    const float* b1d = b1 + (size_t)dir * G4H;
    const float* b2d = b2 + (size_t)dir * G4H;
    float bias[8];
#pragma unroll
    for (int j = 0; j < 8; j++) {
        int n = n0 + tx * 8 + j;
        bias[j] = b1d[n] + b2d[n];
    }
#pragma unroll
    for (int i = 0; i < 8; i++) {
        int m = m0 + ty * 8 + i;
        float* crow = Cd + (size_t)m * G4H + n0 + tx * 8;
        float2 c0 = unpack2(acc2[i][0]);
        float2 c1 = unpack2(acc2[i][1]);
        float2 c2 = unpack2(acc2[i][2]);
        float2 c3 = unpack2(acc2[i][3]);
        float4 o0, o1;
        o0.x = c0.x + bias[0]; o0.y = c0.y + bias[1];
        o0.z = c1.x + bias[2]; o0.w = c1.y + bias[3];
        o1.x = c2.x + bias[4]; o1.y = c2.y + bias[5];
        o1.z = c3.x + bias[6]; o1.w = c3.y + bias[7];
        *(float4*)(crow)     = o0;
        *(float4*)(crow + 4) = o1;
    }
}

// ---------------------------------------------------------------------------
// 3) recurrent scan — R4 protocol exactly, EXCEPT the poll loop is a
//    3-sample software pipeline (no timed spins): each iteration issues a new
//    sample first (non-blocking), then evaluates the oldest (issued two
//    iterations ago). Scoreboard self-paces the loop at ~RTT/2, halving the
//    sampling quantum; fast-path cost identical to R4.
//    grid = 128 CTAs: dir = blk>>6, 64 CTAs/dir, each owns 8 hidden units.
// ---------------------------------------------------------------------------
__global__ void __launch_bounds__(256, 1)
scan_kernel(const float* __restrict__ Whh, int layer) {
    float* hcat = layer ? g_hcat1 : g_hcat0;
    const int dir = blockIdx.x >> 6;
    const int cta = blockIdx.x & 63;
    const int j0 = cta * 8;
    const int tid = threadIdx.x;
    const int row = tid & 31;    // 0..31 : local gate-row
    const int seg = tid >> 5;    // warp id 0..7 : k-segment (64 floats each)
    const int lane = tid & 31;
    const int q = row >> 3, jj = row & 7;
    const int R = q * HD + j0 + jj;            // global gate row in [0,4H)

    // Whh slice in registers as packed pairs: 64 floats = 32 u64
    const ulonglong2* wsrc2 =
        (const ulonglong2*)(Whh + ((size_t)dir * G4H + R) * HD + seg * 64);
    ulonglong2 w2[16];
#pragma unroll
    for (int i = 0; i < 16; i++) w2[i] = wsrc2[i];

    __shared__ __align__(16) float hbuf[8][64];
    __shared__ float part[2][8][32];
    __shared__ float gin[2][32];

    const float* Gd = g_G + (size_t)dir * TSEQ * G4H;
    unsigned long long* myStampBase = g_hstamp + (size_t)dir * 2 * HD;

    // warp7: prefetch G for step 0
    float gnext = 0.0f;
    if (seg == 7) {
        int t0 = dir ? (TSEQ - 1) : 0;
        gnext = __ldg(Gd + (size_t)t0 * G4H + R);
    }

    float creg = 0.0f;   // cell state for unit j0+tid (valid lanes 0..7 of warp0)

    for (int s = 0; s < TSEQ; s++) {
        const int t = dir ? (TSEQ - 1 - s) : s;
        const int par = s & 1;

        // warp 7: stage this step's G (prefetched last step), prefetch next
        if (seg == 7) {
            gin[par][row] = gnext;
            if (s + 1 < TSEQ) {
                int tn = dir ? (TSEQ - 2 - s) : (s + 1);
                gnext = __ldg(Gd + (size_t)tn * G4H + R);
            }
        }

        // each warp polls / fills its own 64-float h segment
        if (s == 0) {
            hbuf[seg][lane * 2]     = 0.0f;
            hbuf[seg][lane * 2 + 1] = 0.0f;
        } else {
            const unsigned long long* src =
                myStampBase + ((size_t)((s + 1) & 1)) * HD + seg * 64 + lane * 2;
            const unsigned need = (unsigned)s;

            // 3-deep pipelined poll: issue-first, evaluate-oldest
            unsigned long long v0 = ld_relaxed_u64(src);
            unsigned long long v1 = ld_relaxed_u64(src + 1);
            unsigned long long u0 = ld_relaxed_u64(src);
            unsigned long long u1 = ld_relaxed_u64(src + 1);
            for (;;) {
                unsigned long long x0 = ld_relaxed_u64(src);
                unsigned long long x1 = ld_relaxed_u64(src + 1);
                bool ok = ((unsigned)(v0 >> 32) >= need) &&
                          ((unsigned)(v1 >> 32) >= need);
                if (__all_sync(0xffffffffu, ok)) break;
                v0 = u0; v1 = u1;
                u0 = x0; u1 = x1;
            }
            hbuf[seg][lane * 2]     = __uint_as_float((unsigned)v0);
            hbuf[seg][lane * 2 + 1] = __uint_as_float((unsigned)v1);
        }
        __syncwarp();

        // packed dot: 32 FFMA2 (64 MACs) registers x smem-broadcast h
        const ulonglong2* hb2 = (const ulonglong2*)hbuf[seg];
        unsigned long long a0 = 0ULL, a1 = 0ULL, a2 = 0ULL, a3 = 0ULL;
#pragma unroll
        for (int i = 0; i < 16; i += 2) {
            ulonglong2 h0 = hb2[i];
            ulonglong2 h1 = hb2[i + 1];
            a0 = ffma2(w2[i].x,     h0.x, a0);
            a1 = ffma2(w2[i].y,     h0.y, a1);
            a2 = ffma2(w2[i + 1].x, h1.x, a2);
            a3 = ffma2(w2[i + 1].y, h1.y, a3);
        }
        float2 f0 = unpack2(a0), f1 = unpack2(a1), f2 = unpack2(a2), f3 = unpack2(a3);
        part[par][seg][row] =
            ((f0.x + f0.y) + (f1.x + f1.y)) + ((f2.x + f2.y) + (f3.x + f3.y));
        __syncthreads();

        // warp 0: reduce across segments, gather gates via SHFL, run cell
        if (tid < 32) {
            float g = gin[par][tid];
#pragma unroll
            for (int p = 0; p < 8; p++) g += part[par][p][tid];
            float fg = __shfl_down_sync(0xffffffffu, g, 8);
            float gg = __shfl_down_sync(0xffffffffu, g, 16);
            float og = __shfl_down_sync(0xffffffffu, g, 24);
            if (tid < 8) {
                float c = sig_hw(fg) * creg + sig_hw(g) * tanh_hw(gg);
                creg = c;
                float h = sig_hw(og) * tanh_hw(c);
                // publish FIRST (unblocks all consumer CTAs), then persist
                unsigned long long pk =
                    ((unsigned long long)(unsigned)(s + 1) << 32) |
                    (unsigned long long)__float_as_uint(h);
                st_relaxed_u64(myStampBase + (size_t)par * HD + j0 + tid, pk);
                hcat[(size_t)t * (2 * HD) + dir * HD + j0 + tid] = h;
            }
        }
    }
}

// ---------------------------------------------------------------------------
// 4) tag projection: feats[t][tag] = hcat1[t] . W_tag[tag] + b_tag[tag]
// ---------------------------------------------------------------------------
__global__ void feats_kernel(const float* __restrict__ Wtag,
                             const float* __restrict__ btag) {
    int t = blockIdx.x;
    __shared__ float xs[2 * HD];
    for (int i = threadIdx.x; i < 2 * HD; i += 192)
        xs[i] = g_hcat1[(size_t)t * (2 * HD) + i];
    __syncthreads();
    int tag = threadIdx.x / 16;
    int sg  = threadIdx.x % 16;
    const float* w = Wtag + (size_t)tag * (2 * HD) + sg * 64;
    const float* x = xs + sg * 64;
    float s = 0.0f;
#pragma unroll
    for (int i = 0; i < 64; i++) s = fmaf(w[i], x[i], s);
#pragma unroll
    for (int o = 8; o > 0; o >>= 1)
        s += __shfl_down_sync(0xffffffffu, s, o, 16);
    if (sg == 0) g_feats[t * NTAGS + tag] = s + btag[tag];
}

// ---------------------------------------------------------------------------
// 5) Viterbi + backtrace (single block; warp0 scans; feats staged in smem)
// ---------------------------------------------------------------------------
#define VIT_SMEM (TSEQ * NTAGS * 4 + TSEQ * NTAGS)

__global__ void viterbi_kernel(const float* __restrict__ trans,
                               float* __restrict__ out, int out_size) {
    extern __shared__ char vsm[];
    float* fsh = (float*)vsm;
    unsigned char* bp = (unsigned char*)(vsm + TSEQ * NTAGS * 4);

    for (int i = threadIdx.x; i < TSEQ * NTAGS; i += blockDim.x)
        fsh[i] = g_feats[i];
    __syncthreads();

    if (threadIdx.x >= 32) return;
    const int lane = threadIdx.x;

    float tr[NTAGS];
    if (lane < NTAGS) {
#pragma unroll
        for (int p = 0; p < NTAGS; p++) tr[p] = trans[lane * NTAGS + p];
    } else {
#pragma unroll
        for (int p = 0; p < NTAGS; p++) tr[p] = -3e38f;
    }

    float fv = (lane == START_TAG) ? 0.0f : ((lane < NTAGS) ? NEGV : -3e38f);
    float featp = (lane < NTAGS) ? fsh[lane] : 0.0f;

    for (int t = 0; t < TSEQ; t++) {
        float featn = (lane < NTAGS && t + 1 < TSEQ) ? fsh[(t + 1) * NTAGS + lane] : 0.0f;
        float best = -3e38f;
        int arg = 0;
#pragma unroll
        for (int p = 0; p < NTAGS; p++) {
            float fp = __shfl_sync(0xffffffffu, fv, p);
            float sc = fp + tr[p];
            if (sc > best) { best = sc; arg = p; }
        }
        if (lane < NTAGS) {
            bp[t * NTAGS + lane] = (unsigned char)arg;
            fv = best + featp;
        } else {
            fv = -3e38f;
        }
        featp = featn;
    }

    float term = (lane < NTAGS) ? fv + trans[STOP_TAG * NTAGS + lane] : -3e38f;
    float bs = term;
    int bi = lane;
#pragma unroll
    for (int o = 16; o > 0; o >>= 1) {
        float os = __shfl_down_sync(0xffffffffu, bs, o);
        int   oi = __shfl_down_sync(0xffffffffu, bi, o);
        if (os > bs || (os == bs && oi < bi)) { bs = os; bi = oi; }
    }
    __syncwarp();

    if (lane == 0) {
        float score = bs;
        int tag = bi;
        if (out_size >= TSEQ + 1) {
            out[0] = score;
            out[TSEQ] = (float)tag;
            for (int t = TSEQ - 1; t >= 1; t--) {
                tag = bp[t * NTAGS + tag];
                out[t] = (float)tag;
            }
            for (int i = TSEQ + 1; i < out_size; i++) out[i] = 0.0f;
        } else {
            int n = out_size;
            if (n > 0) {
                if (TSEQ - 1 < n) out[TSEQ - 1] = (float)tag;
                for (int t = TSEQ - 1; t >= 1; t--) {
                    tag = bp[t * NTAGS + tag];
                    if (t - 1 < n) out[t - 1] = (float)tag;
                }
            }
        }
    }
}

// ---------------------------------------------------------------------------
// launch
// ---------------------------------------------------------------------------
extern "C" void kernel_launch(void* const* d_in, const int* in_sizes, int n_in,
                              void* d_out, int out_size) {
    const int*   sentence = (const int*)  d_in[0];
    const float* emb      = (const float*)d_in[1];
    const float* Wih0     = (const float*)d_in[2];
    const float* Whh0     = (const float*)d_in[3];
    const float* bih0     = (const float*)d_in[4];
    const float* bhh0     = (const float*)d_in[5];
    const float* Wih1     = (const float*)d_in[6];
    const float* Whh1     = (const float*)d_in[7];
    const float* bih1     = (const float*)d_in[8];
    const float* bhh1     = (const float*)d_in[9];
    const float* Wtag     = (const float*)d_in[10];
    const float* btag     = (const float*)d_in[11];
    const float* trans    = (const float*)d_in[12];
    float* out = (float*)d_out;

    cudaFuncSetAttribute(viterbi_kernel,
                         cudaFuncAttributeMaxDynamicSharedMemorySize, VIT_SMEM);

    embed_kernel<<<TSEQ, 128>>>(sentence, emb);

    // ---- layer 0 ----
    init_stamps_kernel<<<4, 512>>>();
    gemm_bias_kernel<<<dim3(16, 16, 2), 256>>>(Wih0, bih0, bhh0, EMB, 0);
    scan_kernel<<<128, 256>>>(Whh0, 0);

    // ---- layer 1 ----
    init_stamps_kernel<<<4, 512>>>();
    gemm_bias_kernel<<<dim3(16, 16, 2), 256>>>(Wih1, bih1, bhh1, 2 * HD, 1);
    scan_kernel<<<128, 256>>>(Whh1, 1);

    // ---- CRF ----
    feats_kernel<<<TSEQ, 192>>>(Wtag, btag);
    viterbi_kernel<<<1, 128, VIT_SMEM>>>(trans, out, out_size);
}

// round 7
// speedup vs baseline: 1.5148x; 1.5148x over previous
#include <cuda_runtime.h>
#include <cuda_bf16.h>
#include <math.h>

// ---------------------------------------------------------------------------
// Problem constants
// ---------------------------------------------------------------------------
#define TSEQ 2048
#define HD   512        // hidden size H
#define EMB  512        // embedding dim E
#define G4H  2048       // 4*H
#define NTAGS 12
#define START_TAG 10
#define STOP_TAG  11
#define NEGV (-10000.0f)

// ---------------------------------------------------------------------------
// Scratch (device globals; no allocations allowed)
// ---------------------------------------------------------------------------
__device__ float g_x0[TSEQ * EMB];                 // embedded input      4 MB
__device__ float g_G[2 * TSEQ * G4H];              // input projections  32 MB (reused per layer)
__device__ float g_hcat0[TSEQ * 2 * HD];           // layer0 output       8 MB
__device__ float g_hcat1[TSEQ * 2 * HD];           // layer1 output       8 MB
__device__ float g_feats[TSEQ * NTAGS];
__device__ unsigned long long g_hstamp[2 * 2 * HD]; // [dir][parity][H] stamped h

// ---------------------------------------------------------------------------
// Helpers
// ---------------------------------------------------------------------------
__device__ __forceinline__ unsigned long long ld_relaxed_u64(const unsigned long long* p) {
    unsigned long long v;
    asm volatile("ld.relaxed.gpu.global.b64 %0, [%1];" : "=l"(v) : "l"(p) : "memory");
    return v;
}
__device__ __forceinline__ void st_relaxed_u64(unsigned long long* p, unsigned long long v) {
    asm volatile("st.relaxed.gpu.global.b64 [%0], %1;" :: "l"(p), "l"(v) : "memory");
}

// packed f32x2 FMA (FFMA2 — only reachable via PTX)
__device__ __forceinline__ unsigned long long ffma2(unsigned long long a,
                                                    unsigned long long b,
                                                    unsigned long long c) {
    unsigned long long d;
    asm("fma.rn.f32x2 %0, %1, %2, %3;" : "=l"(d) : "l"(a), "l"(b), "l"(c));
    return d;
}
__device__ __forceinline__ float2 unpack2(unsigned long long v) {
    float2 r;
    asm("mov.b64 {%0, %1}, %2;" : "=f"(r.x), "=f"(r.y) : "l"(v));
    return r;
}

// HW tanh (MUFU-class, ~1e-5 abs err) and sigmoid via tanh
__device__ __forceinline__ float tanh_hw(float x) {
    float y;
    asm("tanh.approx.f32 %0, %1;" : "=f"(y) : "f"(x));
    return y;
}
__device__ __forceinline__ float sig_hw(float x) {
    return fmaf(0.5f, tanh_hw(0.5f * x), 0.5f);
}

// tf32 conversion (round-to-nearest)
__device__ __forceinline__ unsigned f2tf(float x) {
    unsigned r;
    asm("cvt.rna.tf32.f32 %0, %1;" : "=r"(r) : "f"(x));
    return r;
}

// m16n8k8 tf32 MMA
__device__ __forceinline__ void mma_tf32(float* c, const unsigned* a,
                                         unsigned b0, unsigned b1) {
    asm("mma.sync.aligned.m16n8k8.row.col.f32.tf32.tf32.f32 "
        "{%0,%1,%2,%3}, {%4,%5,%6,%7}, {%8,%9}, {%0,%1,%2,%3};"
        : "+f"(c[0]), "+f"(c[1]), "+f"(c[2]), "+f"(c[3])
        : "r"(a[0]), "r"(a[1]), "r"(a[2]), "r"(a[3]), "r"(b0), "r"(b1));
}

// ---------------------------------------------------------------------------
// 0) reset stamp buffers (must run before each scan launch)
// ---------------------------------------------------------------------------
__global__ void init_stamps_kernel() {
    int i = blockIdx.x * blockDim.x + threadIdx.x;
    if (i < 2 * 2 * HD) g_hstamp[i] = 0ULL;
}

// ---------------------------------------------------------------------------
// 1) embedding gather: x0[t][e] = emb[sentence[t]][e]
// ---------------------------------------------------------------------------
__global__ void embed_kernel(const int* __restrict__ sentence,
                             const float* __restrict__ emb) {
    int t = blockIdx.x;
    int v = sentence[t];
    const float4* src = (const float4*)(emb + (size_t)v * EMB);
    float4* dst = (float4*)(g_x0 + (size_t)t * EMB);
    dst[threadIdx.x] = src[threadIdx.x];   // 128 threads * float4 = 512 floats
}

// ---------------------------------------------------------------------------
// 2) input-projection GEMM — tf32 tensor cores, 3-term split (hh + hl + lh).
//    C[d][t][r] = sum_k A[t][k]*W[d][r][k] + b1[d][r]+b2[d][r]
//    128x128 tile, BK=16, 256 threads = 8 warps laid 4(m) x 2(n);
//    warp tile 32x64 = 2 m16 x 8 n8 mma tiles, fp32 accumulate.
// ---------------------------------------------------------------------------
#define BM 128
#define BN 128
#define BK 16

__global__ void __launch_bounds__(256)
gemm_bias_kernel(const float* __restrict__ W,
                 const float* __restrict__ b1,
                 const float* __restrict__ b2,
                 int K, int layer) {
    const float* A = layer ? g_hcat0 : g_x0;
    __shared__ float As[BK][BM + 4];
    __shared__ float Bs[BK][BN + 4];

    int dir = blockIdx.z;
    const float* Wd = W + (size_t)dir * G4H * K;
    float* Cd = g_G + (size_t)dir * TSEQ * G4H;

    int tid = threadIdx.x;
    int m0 = blockIdx.y * BM, n0 = blockIdx.x * BN;
    int w = tid >> 5, lane = tid & 31;
    int wm = w & 3, wn = w >> 2;     // 4 x 2 warp grid
    int g = lane >> 2, tig = lane & 3;
    int rb = wm * 32;                // warp row base in tile
    int cb = wn * 64;                // warp col base in tile

    float acc[2][8][4];
#pragma unroll
    for (int i = 0; i < 2; i++)
#pragma unroll
        for (int j = 0; j < 8; j++)
#pragma unroll
            for (int r = 0; r < 4; r++) acc[i][j][r] = 0.0f;

    int lr = tid >> 1;            // 0..127
    int lc = (tid & 1) * 8;       // 0 or 8

    for (int k0 = 0; k0 < K; k0 += BK) {
        float4 a0 = *(const float4*)(A  + (size_t)(m0 + lr) * K + k0 + lc);
        float4 a1 = *(const float4*)(A  + (size_t)(m0 + lr) * K + k0 + lc + 4);
        float4 w0 = *(const float4*)(Wd + (size_t)(n0 + lr) * K + k0 + lc);
        float4 w1 = *(const float4*)(Wd + (size_t)(n0 + lr) * K + k0 + lc + 4);
        __syncthreads();
        As[lc + 0][lr] = a0.x; As[lc + 1][lr] = a0.y; As[lc + 2][lr] = a0.z; As[lc + 3][lr] = a0.w;
        As[lc + 4][lr] = a1.x; As[lc + 5][lr] = a1.y; As[lc + 6][lr] = a1.z; As[lc + 7][lr] = a1.w;
        Bs[lc + 0][lr] = w0.x; Bs[lc + 1][lr] = w0.y; Bs[lc + 2][lr] = w0.z; Bs[lc + 3][lr] = w0.w;
        Bs[lc + 4][lr] = w1.x; Bs[lc + 5][lr] = w1.y; Bs[lc + 6][lr] = w1.z; Bs[lc + 7][lr] = w1.w;
        __syncthreads();

#pragma unroll
        for (int ks = 0; ks < BK; ks += 8) {
            // A fragments: hi/lo tf32 split, 2 m-tiles
            unsigned ah[2][4], al[2][4];
#pragma unroll
            for (int mt = 0; mt < 2; mt++) {
                int r0 = rb + mt * 16 + g;
                float x0 = As[ks + tig][r0];
                float x1 = As[ks + tig][r0 + 8];
                float x2 = As[ks + tig + 4][r0];
                float x3 = As[ks + tig + 4][r0 + 8];
                ah[mt][0] = f2tf(x0); al[mt][0] = f2tf(x0 - __uint_as_float(ah[mt][0]));
                ah[mt][1] = f2tf(x1); al[mt][1] = f2tf(x1 - __uint_as_float(ah[mt][1]));
                ah[mt][2] = f2tf(x2); al[mt][2] = f2tf(x2 - __uint_as_float(ah[mt][2]));
                ah[mt][3] = f2tf(x3); al[mt][3] = f2tf(x3 - __uint_as_float(ah[mt][3]));
            }
#pragma unroll
            for (int nt = 0; nt < 8; nt++) {
                int n = cb + nt * 8 + g;
                float y0 = Bs[ks + tig][n];
                float y1 = Bs[ks + tig + 4][n];
                unsigned bh0 = f2tf(y0), bl0 = f2tf(y0 - __uint_as_float(bh0));
                unsigned bh1 = f2tf(y1), bl1 = f2tf(y1 - __uint_as_float(bh1));
#pragma unroll
                for (int mt = 0; mt < 2; mt++) {
                    mma_tf32(acc[mt][nt], ah[mt], bh0, bh1);   // hi*hi
                    mma_tf32(acc[mt][nt], ah[mt], bl0, bl1);   // hi*lo
                    mma_tf32(acc[mt][nt], al[mt], bh0, bh1);   // lo*hi
                }
            }
        }
    }

    const float* b1d = b1 + (size_t)dir * G4H;
    const float* b2d = b2 + (size_t)dir * G4H;
#pragma unroll
    for (int nt = 0; nt < 8; nt++) {
        int n = n0 + cb + nt * 8 + 2 * tig;
        float bias0 = b1d[n]     + b2d[n];
        float bias1 = b1d[n + 1] + b2d[n + 1];
#pragma unroll
        for (int mt = 0; mt < 2; mt++) {
            int row = m0 + rb + mt * 16 + g;
            float2 v0, v1;
            v0.x = acc[mt][nt][0] + bias0;
            v0.y = acc[mt][nt][1] + bias1;
            v1.x = acc[mt][nt][2] + bias0;
            v1.y = acc[mt][nt][3] + bias1;
            *(float2*)(Cd + (size_t)row * G4H + n)       = v0;
            *(float2*)(Cd + (size_t)(row + 8) * G4H + n) = v1;
        }
    }
}

// ---------------------------------------------------------------------------
// 3) recurrent scan — EXACT R4 protocol (best measured: 4392us total).
//    grid = 128 CTAs: dir = blk>>6, 64 CTAs/dir, each owns 8 hidden units.
//    Warp seg computes 64-float k-segment partials for all 32 gate rows
//    (32 FFMA2 per thread); warp0 reduces, gathers gates via SHFL, runs the
//    cell with tanh.approx, publishes stamped h. ONE __syncthreads per step.
// ---------------------------------------------------------------------------
__global__ void __launch_bounds__(256, 1)
scan_kernel(const float* __restrict__ Whh, int layer) {
    float* hcat = layer ? g_hcat1 : g_hcat0;
    const int dir = blockIdx.x >> 6;
    const int cta = blockIdx.x & 63;
    const int j0 = cta * 8;
    const int tid = threadIdx.x;
    const int row = tid & 31;    // 0..31 : local gate-row
    const int seg = tid >> 5;    // warp id 0..7 : k-segment (64 floats each)
    const int lane = tid & 31;
    const int q = row >> 3, jj = row & 7;
    const int R = q * HD + j0 + jj;            // global gate row in [0,4H)

    // Whh slice in registers as packed pairs: 64 floats = 32 u64
    const ulonglong2* wsrc2 =
        (const ulonglong2*)(Whh + ((size_t)dir * G4H + R) * HD + seg * 64);
    ulonglong2 w2[16];
#pragma unroll
    for (int i = 0; i < 16; i++) w2[i] = wsrc2[i];

    __shared__ __align__(16) float hbuf[8][64];
    __shared__ float part[2][8][32];
    __shared__ float gin[2][32];

    const float* Gd = g_G + (size_t)dir * TSEQ * G4H;
    unsigned long long* myStampBase = g_hstamp + (size_t)dir * 2 * HD;

    // warp7: prefetch G for step 0
    float gnext = 0.0f;
    if (seg == 7) {
        int t0 = dir ? (TSEQ - 1) : 0;
        gnext = __ldg(Gd + (size_t)t0 * G4H + R);
    }

    float creg = 0.0f;   // cell state for unit j0+tid (valid lanes 0..7 of warp0)

    for (int s = 0; s < TSEQ; s++) {
        const int t = dir ? (TSEQ - 1 - s) : s;
        const int par = s & 1;

        // warp 7: stage this step's G (prefetched last step), prefetch next
        if (seg == 7) {
            gin[par][row] = gnext;
            if (s + 1 < TSEQ) {
                int tn = dir ? (TSEQ - 2 - s) : (s + 1);
                gnext = __ldg(Gd + (size_t)tn * G4H + R);
            }
        }

        // each warp polls / fills its own 64-float h segment
        if (s == 0) {
            hbuf[seg][lane * 2]     = 0.0f;
            hbuf[seg][lane * 2 + 1] = 0.0f;
        } else {
            const unsigned long long* src =
                myStampBase + ((size_t)((s + 1) & 1)) * HD + seg * 64 + lane * 2;
            const unsigned need = (unsigned)s;
            unsigned long long v0, v1;
            for (;;) {
                v0 = ld_relaxed_u64(src);
                v1 = ld_relaxed_u64(src + 1);
                bool ok = ((unsigned)(v0 >> 32) >= need) && ((unsigned)(v1 >> 32) >= need);
                if (__all_sync(0xffffffffu, ok)) break;
            }
            hbuf[seg][lane * 2]     = __uint_as_float((unsigned)v0);
            hbuf[seg][lane * 2 + 1] = __uint_as_float((unsigned)v1);
        }
        __syncwarp();

        // packed dot: 32 FFMA2 (64 MACs) registers x smem-broadcast h
        const ulonglong2* hb2 = (const ulonglong2*)hbuf[seg];
        unsigned long long a0 = 0ULL, a1 = 0ULL, a2 = 0ULL, a3 = 0ULL;
#pragma unroll
        for (int i = 0; i < 16; i += 2) {
            ulonglong2 h0 = hb2[i];
            ulonglong2 h1 = hb2[i + 1];
            a0 = ffma2(w2[i].x,     h0.x, a0);
            a1 = ffma2(w2[i].y,     h0.y, a1);
            a2 = ffma2(w2[i + 1].x, h1.x, a2);
            a3 = ffma2(w2[i + 1].y, h1.y, a3);
        }
        float2 f0 = unpack2(a0), f1 = unpack2(a1), f2 = unpack2(a2), f3 = unpack2(a3);
        part[par][seg][row] =
            ((f0.x + f0.y) + (f1.x + f1.y)) + ((f2.x + f2.y) + (f3.x + f3.y));
        __syncthreads();

        // warp 0: reduce across segments, gather gates via SHFL, run cell
        if (tid < 32) {
            float g = gin[par][tid];
#pragma unroll
            for (int p = 0; p < 8; p++) g += part[par][p][tid];
            float fg = __shfl_down_sync(0xffffffffu, g, 8);
            float gg = __shfl_down_sync(0xffffffffu, g, 16);
            float og = __shfl_down_sync(0xffffffffu, g, 24);
            if (tid < 8) {
                float c = sig_hw(fg) * creg + sig_hw(g) * tanh_hw(gg);
                creg = c;
                float h = sig_hw(og) * tanh_hw(c);
                // publish FIRST (unblocks all consumer CTAs), then persist
                unsigned long long pk =
                    ((unsigned long long)(unsigned)(s + 1) << 32) |
                    (unsigned long long)__float_as_uint(h);
                st_relaxed_u64(myStampBase + (size_t)par * HD + j0 + tid, pk);
                hcat[(size_t)t * (2 * HD) + dir * HD + j0 + tid] = h;
            }
        }
    }
}

// ---------------------------------------------------------------------------
// 4) tag projection: feats[t][tag] = hcat1[t] . W_tag[tag] + b_tag[tag]
// ---------------------------------------------------------------------------
__global__ void feats_kernel(const float* __restrict__ Wtag,
                             const float* __restrict__ btag) {
    int t = blockIdx.x;
    __shared__ float xs[2 * HD];
    for (int i = threadIdx.x; i < 2 * HD; i += 192)
        xs[i] = g_hcat1[(size_t)t * (2 * HD) + i];
    __syncthreads();
    int tag = threadIdx.x / 16;
    int sg  = threadIdx.x % 16;
    const float* w = Wtag + (size_t)tag * (2 * HD) + sg * 64;
    const float* x = xs + sg * 64;
    float s = 0.0f;
#pragma unroll
    for (int i = 0; i < 64; i++) s = fmaf(w[i], x[i], s);
#pragma unroll
    for (int o = 8; o > 0; o >>= 1)
        s += __shfl_down_sync(0xffffffffu, s, o, 16);
    if (sg == 0) g_feats[t * NTAGS + tag] = s + btag[tag];
}

// ---------------------------------------------------------------------------
// 5) Viterbi + backtrace (single block; warp0 scans; feats staged in smem)
// ---------------------------------------------------------------------------
#define VIT_SMEM (TSEQ * NTAGS * 4 + TSEQ * NTAGS)

__global__ void viterbi_kernel(const float* __restrict__ trans,
                               float* __restrict__ out, int out_size) {
    extern __shared__ char vsm[];
    float* fsh = (float*)vsm;
    unsigned char* bp = (unsigned char*)(vsm + TSEQ * NTAGS * 4);

    for (int i = threadIdx.x; i < TSEQ * NTAGS; i += blockDim.x)
        fsh[i] = g_feats[i];
    __syncthreads();

    if (threadIdx.x >= 32) return;
    const int lane = threadIdx.x;

    float tr[NTAGS];
    if (lane < NTAGS) {
#pragma unroll
        for (int p = 0; p < NTAGS; p++) tr[p] = trans[lane * NTAGS + p];
    } else {
#pragma unroll
        for (int p = 0; p < NTAGS; p++) tr[p] = -3e38f;
    }

    float fv = (lane == START_TAG) ? 0.0f : ((lane < NTAGS) ? NEGV : -3e38f);
    float featp = (lane < NTAGS) ? fsh[lane] : 0.0f;

    for (int t = 0; t < TSEQ; t++) {
        float featn = (lane < NTAGS && t + 1 < TSEQ) ? fsh[(t + 1) * NTAGS + lane] : 0.0f;
        float best = -3e38f;
        int arg = 0;
#pragma unroll
        for (int p = 0; p < NTAGS; p++) {
            float fp = __shfl_sync(0xffffffffu, fv, p);
            float sc = fp + tr[p];
            if (sc > best) { best = sc; arg = p; }
        }
        if (lane < NTAGS) {
            bp[t * NTAGS + lane] = (unsigned char)arg;
            fv = best + featp;
        } else {
            fv = -3e38f;
        }
        featp = featn;
    }

    float term = (lane < NTAGS) ? fv + trans[STOP_TAG * NTAGS + lane] : -3e38f;
    float bs = term;
    int bi = lane;
#pragma unroll
    for (int o = 16; o > 0; o >>= 1) {
        float os = __shfl_down_sync(0xffffffffu, bs, o);
        int   oi = __shfl_down_sync(0xffffffffu, bi, o);
        if (os > bs || (os == bs && oi < bi)) { bs = os; bi = oi; }
    }
    __syncwarp();

    if (lane == 0) {
        float score = bs;
        int tag = bi;
        if (out_size >= TSEQ + 1) {
            out[0] = score;
            out[TSEQ] = (float)tag;
            for (int t = TSEQ - 1; t >= 1; t--) {
                tag = bp[t * NTAGS + tag];
                out[t] = (float)tag;
            }
            for (int i = TSEQ + 1; i < out_size; i++) out[i] = 0.0f;
        } else {
            int n = out_size;
            if (n > 0) {
                if (TSEQ - 1 < n) out[TSEQ - 1] = (float)tag;
                for (int t = TSEQ - 1; t >= 1; t--) {
                    tag = bp[t * NTAGS + tag];
                    if (t - 1 < n) out[t - 1] = (float)tag;
                }
            }
        }
    }
}

// ---------------------------------------------------------------------------
// launch
// ---------------------------------------------------------------------------
extern "C" void kernel_launch(void* const* d_in, const int* in_sizes, int n_in,
                              void* d_out, int out_size) {
    const int*   sentence = (const int*)  d_in[0];
    const float* emb      = (const float*)d_in[1];
    const float* Wih0     = (const float*)d_in[2];
    const float* Whh0     = (const float*)d_in[3];
    const float* bih0     = (const float*)d_in[4];
    const float* bhh0     = (const float*)d_in[5];
    const float* Wih1     = (const float*)d_in[6];
    const float* Whh1     = (const float*)d_in[7];
    const float* bih1     = (const float*)d_in[8];
    const float* bhh1     = (const float*)d_in[9];
    const float* Wtag     = (const float*)d_in[10];
    const float* btag     = (const float*)d_in[11];
    const float* trans    = (const float*)d_in[12];
    float* out = (float*)d_out;

    cudaFuncSetAttribute(viterbi_kernel,
                         cudaFuncAttributeMaxDynamicSharedMemorySize, VIT_SMEM);

    embed_kernel<<<TSEQ, 128>>>(sentence, emb);

    // ---- layer 0 ----
    init_stamps_kernel<<<4, 512>>>();
    gemm_bias_kernel<<<dim3(16, 16, 2), 256>>>(Wih0, bih0, bhh0, EMB, 0);
    scan_kernel<<<128, 256>>>(Whh0, 0);

    // ---- layer 1 ----
    init_stamps_kernel<<<4, 512>>>();
    gemm_bias_kernel<<<dim3(16, 16, 2), 256>>>(Wih1, bih1, bhh1, 2 * HD, 1);
    scan_kernel<<<128, 256>>>(Whh1, 1);

    // ---- CRF ----
    feats_kernel<<<TSEQ, 192>>>(Wtag, btag);
    viterbi_kernel<<<1, 128, VIT_SMEM>>>(trans, out, out_size);
}

// round 8
// speedup vs baseline: 1.6741x; 1.1052x over previous
#include <cuda_runtime.h>
#include <cuda_bf16.h>
#include <math.h>

// ---------------------------------------------------------------------------
// Problem constants
// ---------------------------------------------------------------------------
#define TSEQ 2048
#define HD   512        // hidden size H
#define EMB  512        // embedding dim E
#define G4H  2048       // 4*H
#define NTAGS 12
#define START_TAG 10
#define STOP_TAG  11
#define NEGV (-10000.0f)

// ---------------------------------------------------------------------------
// Scratch (device globals; no allocations allowed)
// ---------------------------------------------------------------------------
__device__ float g_x0[TSEQ * EMB];                 // embedded input      4 MB
__device__ float g_G[2 * TSEQ * G4H];              // input projections  32 MB (reused per layer)
__device__ float g_hcat0[TSEQ * 2 * HD];           // layer0 output       8 MB
__device__ float g_hcat1[TSEQ * 2 * HD];           // layer1 output       8 MB
__device__ float g_feats[TSEQ * NTAGS];
__device__ unsigned long long g_hstamp[2 * 2 * HD]; // [dir][parity][H] stamped h

// ---------------------------------------------------------------------------
// Helpers
// ---------------------------------------------------------------------------
__device__ __forceinline__ unsigned long long ld_relaxed_u64(const unsigned long long* p) {
    unsigned long long v;
    asm volatile("ld.relaxed.gpu.global.b64 %0, [%1];" : "=l"(v) : "l"(p) : "memory");
    return v;
}
__device__ __forceinline__ void st_relaxed_u64(unsigned long long* p, unsigned long long v) {
    asm volatile("st.relaxed.gpu.global.b64 [%0], %1;" :: "l"(p), "l"(v) : "memory");
}

// packed f32x2 FMA (FFMA2 — only reachable via PTX)
__device__ __forceinline__ unsigned long long ffma2(unsigned long long a,
                                                    unsigned long long b,
                                                    unsigned long long c) {
    unsigned long long d;
    asm("fma.rn.f32x2 %0, %1, %2, %3;" : "=l"(d) : "l"(a), "l"(b), "l"(c));
    return d;
}
__device__ __forceinline__ float2 unpack2(unsigned long long v) {
    float2 r;
    asm("mov.b64 {%0, %1}, %2;" : "=f"(r.x), "=f"(r.y) : "l"(v));
    return r;
}

// HW tanh (MUFU-class, ~1e-5 abs err) and sigmoid via tanh
__device__ __forceinline__ float tanh_hw(float x) {
    float y;
    asm("tanh.approx.f32 %0, %1;" : "=f"(y) : "f"(x));
    return y;
}
__device__ __forceinline__ float sig_hw(float x) {
    return fmaf(0.5f, tanh_hw(0.5f * x), 0.5f);
}

// tf32 conversion (round-to-nearest)
__device__ __forceinline__ unsigned f2tf(float x) {
    unsigned r;
    asm("cvt.rna.tf32.f32 %0, %1;" : "=r"(r) : "f"(x));
    return r;
}

// m16n8k8 tf32 MMA
__device__ __forceinline__ void mma_tf32(float* c, const unsigned* a,
                                         unsigned b0, unsigned b1) {
    asm("mma.sync.aligned.m16n8k8.row.col.f32.tf32.tf32.f32 "
        "{%0,%1,%2,%3}, {%4,%5,%6,%7}, {%8,%9}, {%0,%1,%2,%3};"
        : "+f"(c[0]), "+f"(c[1]), "+f"(c[2]), "+f"(c[3])
        : "r"(a[0]), "r"(a[1]), "r"(a[2]), "r"(a[3]), "r"(b0), "r"(b1));
}

// ---------------------------------------------------------------------------
// 0) reset stamp buffers (must run before each scan launch)
// ---------------------------------------------------------------------------
__global__ void init_stamps_kernel() {
    int i = blockIdx.x * blockDim.x + threadIdx.x;
    if (i < 2 * 2 * HD) g_hstamp[i] = 0ULL;
}

// ---------------------------------------------------------------------------
// 1) embedding gather: x0[t][e] = emb[sentence[t]][e]
// ---------------------------------------------------------------------------
__global__ void embed_kernel(const int* __restrict__ sentence,
                             const float* __restrict__ emb) {
    int t = blockIdx.x;
    int v = sentence[t];
    const float4* src = (const float4*)(emb + (size_t)v * EMB);
    float4* dst = (float4*)(g_x0 + (size_t)t * EMB);
    dst[threadIdx.x] = src[threadIdx.x];   // 128 threads * float4 = 512 floats
}

// ---------------------------------------------------------------------------
// 2) input-projection GEMM — tf32 tensor cores, 3-term split (hh + hl + lh).
//    Conversions hoisted to smem staging: Ah/Al/Bh/Bl hold tf32 hi/lo parts.
//    Inner loop = pure conflict-free LDS.32 + MMA (tensor pipe).
//    128x128 tile, BK=16, 256 threads = 8 warps laid 4(m) x 2(n);
//    warp tile 32x64 = 2 m16 x 8 n8 mma tiles, fp32 accumulate.
// ---------------------------------------------------------------------------
#define BM 128
#define BN 128
#define BK 16
#define PAD 136   // smem row stride (words): (8*row+col)%32 conflict-free

__global__ void __launch_bounds__(256)
gemm_bias_kernel(const float* __restrict__ W,
                 const float* __restrict__ b1,
                 const float* __restrict__ b2,
                 int K, int layer) {
    const float* A = layer ? g_hcat0 : g_x0;
    __shared__ unsigned Ah[BK][PAD], Al[BK][PAD];
    __shared__ unsigned Bh[BK][PAD], Bl[BK][PAD];

    int dir = blockIdx.z;
    const float* Wd = W + (size_t)dir * G4H * K;
    float* Cd = g_G + (size_t)dir * TSEQ * G4H;

    int tid = threadIdx.x;
    int m0 = blockIdx.y * BM, n0 = blockIdx.x * BN;
    int w = tid >> 5, lane = tid & 31;
    int wm = w & 3, wn = w >> 2;     // 4 x 2 warp grid
    int g = lane >> 2, tig = lane & 3;
    int rb = wm * 32;                // warp row base in tile
    int cb = wn * 64;                // warp col base in tile

    float acc[2][8][4];
#pragma unroll
    for (int i = 0; i < 2; i++)
#pragma unroll
        for (int j = 0; j < 8; j++)
#pragma unroll
            for (int r = 0; r < 4; r++) acc[i][j][r] = 0.0f;

    int lr = tid >> 1;            // 0..127
    int lc = (tid & 1) * 8;       // 0 or 8

    for (int k0 = 0; k0 < K; k0 += BK) {
        float av[8], wv[8];
        *(float4*)(av)     = *(const float4*)(A  + (size_t)(m0 + lr) * K + k0 + lc);
        *(float4*)(av + 4) = *(const float4*)(A  + (size_t)(m0 + lr) * K + k0 + lc + 4);
        *(float4*)(wv)     = *(const float4*)(Wd + (size_t)(n0 + lr) * K + k0 + lc);
        *(float4*)(wv + 4) = *(const float4*)(Wd + (size_t)(n0 + lr) * K + k0 + lc + 4);
        __syncthreads();
#pragma unroll
        for (int i = 0; i < 8; i++) {
            unsigned hi = f2tf(av[i]);
            Ah[lc + i][lr] = hi;
            Al[lc + i][lr] = f2tf(av[i] - __uint_as_float(hi));
            unsigned wh = f2tf(wv[i]);
            Bh[lc + i][lr] = wh;
            Bl[lc + i][lr] = f2tf(wv[i] - __uint_as_float(wh));
        }
        __syncthreads();

#pragma unroll
        for (int ks = 0; ks < BK; ks += 8) {
            unsigned ah[2][4], al[2][4];
#pragma unroll
            for (int mt = 0; mt < 2; mt++) {
                int r0 = rb + mt * 16 + g;
                ah[mt][0] = Ah[ks + tig][r0];
                ah[mt][1] = Ah[ks + tig][r0 + 8];
                ah[mt][2] = Ah[ks + tig + 4][r0];
                ah[mt][3] = Ah[ks + tig + 4][r0 + 8];
                al[mt][0] = Al[ks + tig][r0];
                al[mt][1] = Al[ks + tig][r0 + 8];
                al[mt][2] = Al[ks + tig + 4][r0];
                al[mt][3] = Al[ks + tig + 4][r0 + 8];
            }
#pragma unroll
            for (int nt = 0; nt < 8; nt++) {
                int n = cb + nt * 8 + g;
                unsigned bh0 = Bh[ks + tig][n];
                unsigned bh1 = Bh[ks + tig + 4][n];
                unsigned bl0 = Bl[ks + tig][n];
                unsigned bl1 = Bl[ks + tig + 4][n];
#pragma unroll
                for (int mt = 0; mt < 2; mt++) {
                    mma_tf32(acc[mt][nt], ah[mt], bh0, bh1);   // hi*hi
                    mma_tf32(acc[mt][nt], ah[mt], bl0, bl1);   // hi*lo
                    mma_tf32(acc[mt][nt], al[mt], bh0, bh1);   // lo*hi
                }
            }
        }
    }

    const float* b1d = b1 + (size_t)dir * G4H;
    const float* b2d = b2 + (size_t)dir * G4H;
#pragma unroll
    for (int nt = 0; nt < 8; nt++) {
        int n = n0 + cb + nt * 8 + 2 * tig;
        float bias0 = b1d[n]     + b2d[n];
        float bias1 = b1d[n + 1] + b2d[n + 1];
#pragma unroll
        for (int mt = 0; mt < 2; mt++) {
            int row = m0 + rb + mt * 16 + g;
            float2 v0, v1;
            v0.x = acc[mt][nt][0] + bias0;
            v0.y = acc[mt][nt][1] + bias1;
            v1.x = acc[mt][nt][2] + bias0;
            v1.y = acc[mt][nt][3] + bias1;
            *(float2*)(Cd + (size_t)row * G4H + n)       = v0;
            *(float2*)(Cd + (size_t)(row + 8) * G4H + n) = v1;
        }
    }
}

// ---------------------------------------------------------------------------
// 3) recurrent scan — EXACT R4 protocol (best measured).
//    grid = 128 CTAs: dir = blk>>6, 64 CTAs/dir, each owns 8 hidden units.
//    Warp seg computes 64-float k-segment partials for all 32 gate rows
//    (32 FFMA2 per thread); warp0 reduces, gathers gates via SHFL, runs the
//    cell with tanh.approx, publishes stamped h. ONE __syncthreads per step.
// ---------------------------------------------------------------------------
__global__ void __launch_bounds__(256, 1)
scan_kernel(const float* __restrict__ Whh, int layer) {
    float* hcat = layer ? g_hcat1 : g_hcat0;
    const int dir = blockIdx.x >> 6;
    const int cta = blockIdx.x & 63;
    const int j0 = cta * 8;
    const int tid = threadIdx.x;
    const int row = tid & 31;    // 0..31 : local gate-row
    const int seg = tid >> 5;    // warp id 0..7 : k-segment (64 floats each)
    const int lane = tid & 31;
    const int q = row >> 3, jj = row & 7;
    const int R = q * HD + j0 + jj;            // global gate row in [0,4H)

    // Whh slice in registers as packed pairs: 64 floats = 32 u64
    const ulonglong2* wsrc2 =
        (const ulonglong2*)(Whh + ((size_t)dir * G4H + R) * HD + seg * 64);
    ulonglong2 w2[16];
#pragma unroll
    for (int i = 0; i < 16; i++) w2[i] = wsrc2[i];

    __shared__ __align__(16) float hbuf[8][64];
    __shared__ float part[2][8][32];
    __shared__ float gin[2][32];

    const float* Gd = g_G + (size_t)dir * TSEQ * G4H;
    unsigned long long* myStampBase = g_hstamp + (size_t)dir * 2 * HD;

    // warp7: prefetch G for step 0
    float gnext = 0.0f;
    if (seg == 7) {
        int t0 = dir ? (TSEQ - 1) : 0;
        gnext = __ldg(Gd + (size_t)t0 * G4H + R);
    }

    float creg = 0.0f;   // cell state for unit j0+tid (valid lanes 0..7 of warp0)

    for (int s = 0; s < TSEQ; s++) {
        const int t = dir ? (TSEQ - 1 - s) : s;
        const int par = s & 1;

        // warp 7: stage this step's G (prefetched last step), prefetch next
        if (seg == 7) {
            gin[par][row] = gnext;
            if (s + 1 < TSEQ) {
                int tn = dir ? (TSEQ - 2 - s) : (s + 1);
                gnext = __ldg(Gd + (size_t)tn * G4H + R);
            }
        }

        // each warp polls / fills its own 64-float h segment
        if (s == 0) {
            hbuf[seg][lane * 2]     = 0.0f;
            hbuf[seg][lane * 2 + 1] = 0.0f;
        } else {
            const unsigned long long* src =
                myStampBase + ((size_t)((s + 1) & 1)) * HD + seg * 64 + lane * 2;
            const unsigned need = (unsigned)s;
            unsigned long long v0, v1;
            for (;;) {
                v0 = ld_relaxed_u64(src);
                v1 = ld_relaxed_u64(src + 1);
                bool ok = ((unsigned)(v0 >> 32) >= need) && ((unsigned)(v1 >> 32) >= need);
                if (__all_sync(0xffffffffu, ok)) break;
            }
            hbuf[seg][lane * 2]     = __uint_as_float((unsigned)v0);
            hbuf[seg][lane * 2 + 1] = __uint_as_float((unsigned)v1);
        }
        __syncwarp();

        // packed dot: 32 FFMA2 (64 MACs) registers x smem-broadcast h
        const ulonglong2* hb2 = (const ulonglong2*)hbuf[seg];
        unsigned long long a0 = 0ULL, a1 = 0ULL, a2 = 0ULL, a3 = 0ULL;
#pragma unroll
        for (int i = 0; i < 16; i += 2) {
            ulonglong2 h0 = hb2[i];
            ulonglong2 h1 = hb2[i + 1];
            a0 = ffma2(w2[i].x,     h0.x, a0);
            a1 = ffma2(w2[i].y,     h0.y, a1);
            a2 = ffma2(w2[i + 1].x, h1.x, a2);
            a3 = ffma2(w2[i + 1].y, h1.y, a3);
        }
        float2 f0 = unpack2(a0), f1 = unpack2(a1), f2 = unpack2(a2), f3 = unpack2(a3);
        part[par][seg][row] =
            ((f0.x + f0.y) + (f1.x + f1.y)) + ((f2.x + f2.y) + (f3.x + f3.y));
        __syncthreads();

        // warp 0: reduce across segments, gather gates via SHFL, run cell
        if (tid < 32) {
            float g = gin[par][tid];
#pragma unroll
            for (int p = 0; p < 8; p++) g += part[par][p][tid];
            float fg = __shfl_down_sync(0xffffffffu, g, 8);
            float gg = __shfl_down_sync(0xffffffffu, g, 16);
            float og = __shfl_down_sync(0xffffffffu, g, 24);
            if (tid < 8) {
                float c = sig_hw(fg) * creg + sig_hw(g) * tanh_hw(gg);
                creg = c;
                float h = sig_hw(og) * tanh_hw(c);
                // publish FIRST (unblocks all consumer CTAs), then persist
                unsigned long long pk =
                    ((unsigned long long)(unsigned)(s + 1) << 32) |
                    (unsigned long long)__float_as_uint(h);
                st_relaxed_u64(myStampBase + (size_t)par * HD + j0 + tid, pk);
                hcat[(size_t)t * (2 * HD) + dir * HD + j0 + tid] = h;
            }
        }
    }
}

// ---------------------------------------------------------------------------
// 4) tag projection: feats[t][tag] = hcat1[t] . W_tag[tag] + b_tag[tag]
// ---------------------------------------------------------------------------
__global__ void feats_kernel(const float* __restrict__ Wtag,
                             const float* __restrict__ btag) {
    int t = blockIdx.x;
    __shared__ float xs[2 * HD];
    for (int i = threadIdx.x; i < 2 * HD; i += 192)
        xs[i] = g_hcat1[(size_t)t * (2 * HD) + i];
    __syncthreads();
    int tag = threadIdx.x / 16;
    int sg  = threadIdx.x % 16;
    const float* w = Wtag + (size_t)tag * (2 * HD) + sg * 64;
    const float* x = xs + sg * 64;
    float s = 0.0f;
#pragma unroll
    for (int i = 0; i < 64; i++) s = fmaf(w[i], x[i], s);
#pragma unroll
    for (int o = 8; o > 0; o >>= 1)
        s += __shfl_down_sync(0xffffffffu, s, o, 16);
    if (sg == 0) g_feats[t * NTAGS + tag] = s + btag[tag];
}

// ---------------------------------------------------------------------------
// 5) Viterbi + backtrace (single block; warp0 scans; feats staged in smem)
// ---------------------------------------------------------------------------
#define VIT_SMEM (TSEQ * NTAGS * 4 + TSEQ * NTAGS)

__global__ void viterbi_kernel(const float* __restrict__ trans,
                               float* __restrict__ out, int out_size) {
    extern __shared__ char vsm[];
    float* fsh = (float*)vsm;
    unsigned char* bp = (unsigned char*)(vsm + TSEQ * NTAGS * 4);

    for (int i = threadIdx.x; i < TSEQ * NTAGS; i += blockDim.x)
        fsh[i] = g_feats[i];
    __syncthreads();

    if (threadIdx.x >= 32) return;
    const int lane = threadIdx.x;

    float tr[NTAGS];
    if (lane < NTAGS) {
#pragma unroll
        for (int p = 0; p < NTAGS; p++) tr[p] = trans[lane * NTAGS + p];
    } else {
#pragma unroll
        for (int p = 0; p < NTAGS; p++) tr[p] = -3e38f;
    }

    float fv = (lane == START_TAG) ? 0.0f : ((lane < NTAGS) ? NEGV : -3e38f);
    float featp = (lane < NTAGS) ? fsh[lane] : 0.0f;

    for (int t = 0; t < TSEQ; t++) {
        float featn = (lane < NTAGS && t + 1 < TSEQ) ? fsh[(t + 1) * NTAGS + lane] : 0.0f;
        float best = -3e38f;
        int arg = 0;
#pragma unroll
        for (int p = 0; p < NTAGS; p++) {
            float fp = __shfl_sync(0xffffffffu, fv, p);
            float sc = fp + tr[p];
            if (sc > best) { best = sc; arg = p; }
        }
        if (lane < NTAGS) {
            bp[t * NTAGS + lane] = (unsigned char)arg;
            fv = best + featp;
        } else {
            fv = -3e38f;
        }
        featp = featn;
    }

    float term = (lane < NTAGS) ? fv + trans[STOP_TAG * NTAGS + lane] : -3e38f;
    float bs = term;
    int bi = lane;
#pragma unroll
    for (int o = 16; o > 0; o >>= 1) {
        float os = __shfl_down_sync(0xffffffffu, bs, o);
        int   oi = __shfl_down_sync(0xffffffffu, bi, o);
        if (os > bs || (os == bs && oi < bi)) { bs = os; bi = oi; }
    }
    __syncwarp();

    if (lane == 0) {
        float score = bs;
        int tag = bi;
        if (out_size >= TSEQ + 1) {
            out[0] = score;
            out[TSEQ] = (float)tag;
            for (int t = TSEQ - 1; t >= 1; t--) {
                tag = bp[t * NTAGS + tag];
                out[t] = (float)tag;
            }
            for (int i = TSEQ + 1; i < out_size; i++) out[i] = 0.0f;
        } else {
            int n = out_size;
            if (n > 0) {
                if (TSEQ - 1 < n) out[TSEQ - 1] = (float)tag;
                for (int t = TSEQ - 1; t >= 1; t--) {
                    tag = bp[t * NTAGS + tag];
                    if (t - 1 < n) out[t - 1] = (float)tag;
                }
            }
        }
    }
}

// ---------------------------------------------------------------------------
// launch
// ---------------------------------------------------------------------------
extern "C" void kernel_launch(void* const* d_in, const int* in_sizes, int n_in,
                              void* d_out, int out_size) {
    const int*   sentence = (const int*)  d_in[0];
    const float* emb      = (const float*)d_in[1];
    const float* Wih0     = (const float*)d_in[2];
    const float* Whh0     = (const float*)d_in[3];
    const float* bih0     = (const float*)d_in[4];
    const float* bhh0     = (const float*)d_in[5];
    const float* Wih1     = (const float*)d_in[6];
    const float* Whh1     = (const float*)d_in[7];
    const float* bih1     = (const float*)d_in[8];
    const float* bhh1     = (const float*)d_in[9];
    const float* Wtag     = (const float*)d_in[10];
    const float* btag     = (const float*)d_in[11];
    const float* trans    = (const float*)d_in[12];
    float* out = (float*)d_out;

    cudaFuncSetAttribute(viterbi_kernel,
                         cudaFuncAttributeMaxDynamicSharedMemorySize, VIT_SMEM);

    embed_kernel<<<TSEQ, 128>>>(sentence, emb);

    // ---- layer 0 ----
    init_stamps_kernel<<<4, 512>>>();
    gemm_bias_kernel<<<dim3(16, 16, 2), 256>>>(Wih0, bih0, bhh0, EMB, 0);
    scan_kernel<<<128, 256>>>(Whh0, 0);

    // ---- layer 1 ----
    init_stamps_kernel<<<4, 512>>>();
    gemm_bias_kernel<<<dim3(16, 16, 2), 256>>>(Wih1, bih1, bhh1, 2 * HD, 1);
    scan_kernel<<<128, 256>>>(Whh1, 1);

    // ---- CRF ----
    feats_kernel<<<TSEQ, 192>>>(Wtag, btag);
    viterbi_kernel<<<1, 128, VIT_SMEM>>>(trans, out, out_size);
}

// round 9
// speedup vs baseline: 1.6970x; 1.0137x over previous
#include <cuda_runtime.h>
#include <cuda_bf16.h>
#include <math.h>

// ---------------------------------------------------------------------------
// Problem constants
// ---------------------------------------------------------------------------
#define TSEQ 2048
#define HD   512        // hidden size H
#define EMB  512        // embedding dim E
#define G4H  2048       // 4*H
#define NTAGS 12
#define START_TAG 10
#define STOP_TAG  11
#define NEGV (-10000.0f)

// ---------------------------------------------------------------------------
// Scratch (device globals; no allocations allowed)
// ---------------------------------------------------------------------------
__device__ float g_x0[TSEQ * EMB];                 // embedded input      4 MB
__device__ float g_G[2 * TSEQ * G4H];              // input projections  32 MB (reused per layer)
__device__ float g_hcat0[TSEQ * 2 * HD];           // layer0 output       8 MB
__device__ float g_hcat1[TSEQ * 2 * HD];           // layer1 output       8 MB
__device__ float g_feats[TSEQ * NTAGS];
__device__ unsigned long long g_hstamp[2 * 2 * HD]; // [dir][parity][H] stamped h

// ---------------------------------------------------------------------------
// Helpers
// ---------------------------------------------------------------------------
__device__ __forceinline__ unsigned long long ld_relaxed_u64(const unsigned long long* p) {
    unsigned long long v;
    asm volatile("ld.relaxed.gpu.global.b64 %0, [%1];" : "=l"(v) : "l"(p) : "memory");
    return v;
}
__device__ __forceinline__ void st_relaxed_u64(unsigned long long* p, unsigned long long v) {
    asm volatile("st.relaxed.gpu.global.b64 [%0], %1;" :: "l"(p), "l"(v) : "memory");
}

// packed f32x2 FMA (FFMA2 — only reachable via PTX)
__device__ __forceinline__ unsigned long long ffma2(unsigned long long a,
                                                    unsigned long long b,
                                                    unsigned long long c) {
    unsigned long long d;
    asm("fma.rn.f32x2 %0, %1, %2, %3;" : "=l"(d) : "l"(a), "l"(b), "l"(c));
    return d;
}
__device__ __forceinline__ float2 unpack2(unsigned long long v) {
    float2 r;
    asm("mov.b64 {%0, %1}, %2;" : "=f"(r.x), "=f"(r.y) : "l"(v));
    return r;
}

// HW tanh (MUFU-class, ~1e-5 abs err) and sigmoid via tanh
__device__ __forceinline__ float tanh_hw(float x) {
    float y;
    asm("tanh.approx.f32 %0, %1;" : "=f"(y) : "f"(x));
    return y;
}
__device__ __forceinline__ float sig_hw(float x) {
    return fmaf(0.5f, tanh_hw(0.5f * x), 0.5f);
}

// tf32 conversion (round-to-nearest)
__device__ __forceinline__ unsigned f2tf(float x) {
    unsigned r;
    asm("cvt.rna.tf32.f32 %0, %1;" : "=r"(r) : "f"(x));
    return r;
}

// m16n8k8 tf32 MMA
__device__ __forceinline__ void mma_tf32(float* c, const unsigned* a,
                                         unsigned b0, unsigned b1) {
    asm("mma.sync.aligned.m16n8k8.row.col.f32.tf32.tf32.f32 "
        "{%0,%1,%2,%3}, {%4,%5,%6,%7}, {%8,%9}, {%0,%1,%2,%3};"
        : "+f"(c[0]), "+f"(c[1]), "+f"(c[2]), "+f"(c[3])
        : "r"(a[0]), "r"(a[1]), "r"(a[2]), "r"(a[3]), "r"(b0), "r"(b1));
}

// named barriers (count must be multiple of 32)
__device__ __forceinline__ void bar_sync(int id, int cnt) {
    asm volatile("bar.sync %0, %1;" :: "r"(id), "r"(cnt) : "memory");
}
__device__ __forceinline__ void bar_arrive(int id, int cnt) {
    asm volatile("bar.arrive %0, %1;" :: "r"(id), "r"(cnt) : "memory");
}

// ---------------------------------------------------------------------------
// 0) reset stamp buffers (must run before each scan launch)
// ---------------------------------------------------------------------------
__global__ void init_stamps_kernel() {
    int i = blockIdx.x * blockDim.x + threadIdx.x;
    if (i < 2 * 2 * HD) g_hstamp[i] = 0ULL;
}

// ---------------------------------------------------------------------------
// 1) embedding gather: x0[t][e] = emb[sentence[t]][e]
// ---------------------------------------------------------------------------
__global__ void embed_kernel(const int* __restrict__ sentence,
                             const float* __restrict__ emb) {
    int t = blockIdx.x;
    int v = sentence[t];
    const float4* src = (const float4*)(emb + (size_t)v * EMB);
    float4* dst = (float4*)(g_x0 + (size_t)t * EMB);
    dst[threadIdx.x] = src[threadIdx.x];   // 128 threads * float4 = 512 floats
}

// ---------------------------------------------------------------------------
// 2) input-projection GEMM — tf32 tensor cores, 3-term split (hh + hl + lh).
//    Conversions hoisted to smem staging (proved out in R8).
// ---------------------------------------------------------------------------
#define BM 128
#define BN 128
#define BK 16
#define PAD 136   // smem row stride (words): conflict-free

__global__ void __launch_bounds__(256)
gemm_bias_kernel(const float* __restrict__ W,
                 const float* __restrict__ b1,
                 const float* __restrict__ b2,
                 int K, int layer) {
    const float* A = layer ? g_hcat0 : g_x0;
    __shared__ unsigned Ah[BK][PAD], Al[BK][PAD];
    __shared__ unsigned Bh[BK][PAD], Bl[BK][PAD];

    int dir = blockIdx.z;
    const float* Wd = W + (size_t)dir * G4H * K;
    float* Cd = g_G + (size_t)dir * TSEQ * G4H;

    int tid = threadIdx.x;
    int m0 = blockIdx.y * BM, n0 = blockIdx.x * BN;
    int w = tid >> 5, lane = tid & 31;
    int wm = w & 3, wn = w >> 2;     // 4 x 2 warp grid
    int g = lane >> 2, tig = lane & 3;
    int rb = wm * 32;                // warp row base in tile
    int cb = wn * 64;                // warp col base in tile

    float acc[2][8][4];
#pragma unroll
    for (int i = 0; i < 2; i++)
#pragma unroll
        for (int j = 0; j < 8; j++)
#pragma unroll
            for (int r = 0; r < 4; r++) acc[i][j][r] = 0.0f;

    int lr = tid >> 1;            // 0..127
    int lc = (tid & 1) * 8;       // 0 or 8

    for (int k0 = 0; k0 < K; k0 += BK) {
        float av[8], wv[8];
        *(float4*)(av)     = *(const float4*)(A  + (size_t)(m0 + lr) * K + k0 + lc);
        *(float4*)(av + 4) = *(const float4*)(A  + (size_t)(m0 + lr) * K + k0 + lc + 4);
        *(float4*)(wv)     = *(const float4*)(Wd + (size_t)(n0 + lr) * K + k0 + lc);
        *(float4*)(wv + 4) = *(const float4*)(Wd + (size_t)(n0 + lr) * K + k0 + lc + 4);
        __syncthreads();
#pragma unroll
        for (int i = 0; i < 8; i++) {
            unsigned hi = f2tf(av[i]);
            Ah[lc + i][lr] = hi;
            Al[lc + i][lr] = f2tf(av[i] - __uint_as_float(hi));
            unsigned wh = f2tf(wv[i]);
            Bh[lc + i][lr] = wh;
            Bl[lc + i][lr] = f2tf(wv[i] - __uint_as_float(wh));
        }
        __syncthreads();

#pragma unroll
        for (int ks = 0; ks < BK; ks += 8) {
            unsigned ah[2][4], al[2][4];
#pragma unroll
            for (int mt = 0; mt < 2; mt++) {
                int r0 = rb + mt * 16 + g;
                ah[mt][0] = Ah[ks + tig][r0];
                ah[mt][1] = Ah[ks + tig][r0 + 8];
                ah[mt][2] = Ah[ks + tig + 4][r0];
                ah[mt][3] = Ah[ks + tig + 4][r0 + 8];
                al[mt][0] = Al[ks + tig][r0];
                al[mt][1] = Al[ks + tig][r0 + 8];
                al[mt][2] = Al[ks + tig + 4][r0];
                al[mt][3] = Al[ks + tig + 4][r0 + 8];
            }
#pragma unroll
            for (int nt = 0; nt < 8; nt++) {
                int n = cb + nt * 8 + g;
                unsigned bh0 = Bh[ks + tig][n];
                unsigned bh1 = Bh[ks + tig + 4][n];
                unsigned bl0 = Bl[ks + tig][n];
                unsigned bl1 = Bl[ks + tig + 4][n];
#pragma unroll
                for (int mt = 0; mt < 2; mt++) {
                    mma_tf32(acc[mt][nt], ah[mt], bh0, bh1);   // hi*hi
                    mma_tf32(acc[mt][nt], ah[mt], bl0, bl1);   // hi*lo
                    mma_tf32(acc[mt][nt], al[mt], bh0, bh1);   // lo*hi
                }
            }
        }
    }

    const float* b1d = b1 + (size_t)dir * G4H;
    const float* b2d = b2 + (size_t)dir * G4H;
#pragma unroll
    for (int nt = 0; nt < 8; nt++) {
        int n = n0 + cb + nt * 8 + 2 * tig;
        float bias0 = b1d[n]     + b2d[n];
        float bias1 = b1d[n + 1] + b2d[n + 1];
#pragma unroll
        for (int mt = 0; mt < 2; mt++) {
            int row = m0 + rb + mt * 16 + g;
            float2 v0, v1;
            v0.x = acc[mt][nt][0] + bias0;
            v0.y = acc[mt][nt][1] + bias1;
            v1.x = acc[mt][nt][2] + bias0;
            v1.y = acc[mt][nt][3] + bias1;
            *(float2*)(Cd + (size_t)row * G4H + n)       = v0;
            *(float2*)(Cd + (size_t)(row + 8) * G4H + n) = v1;
        }
    }
}

// ---------------------------------------------------------------------------
// 3) recurrent scan — warp-specialized: 8 producer warps + 1 cell warp,
//    parity-split named barriers (A0=id1, A1=id2) instead of __syncthreads.
//    Safety: a producer's poll at step s can only complete after every CTA's
//    warp0 published step s-1, which required ALL producer arrivals for s-1
//    (induction over steps) -> same-parity arrivals cannot mix across steps,
//    and 2-deep part/gin parity buffers remain sufficient (no backpressure
//    barrier needed).
//    grid = 128 CTAs: dir = blk>>6, 64 CTAs/dir, each owns 8 hidden units.
// ---------------------------------------------------------------------------
#define SCAN_THREADS 288   // 9 warps

__global__ void __launch_bounds__(SCAN_THREADS, 1)
scan_kernel(const float* __restrict__ Whh, int layer) {
    float* hcat = layer ? g_hcat1 : g_hcat0;
    const int dir  = blockIdx.x >> 6;
    const int cta  = blockIdx.x & 63;
    const int j0   = cta * 8;
    const int tid  = threadIdx.x;
    const int w    = tid >> 5;       // 0 = cell warp; 1..8 = producers
    const int lane = tid & 31;

    __shared__ __align__(16) float hbuf[8][64];
    __shared__ float part[2][8][32];
    __shared__ float gin[2][32];

    const float* Gd = g_G + (size_t)dir * TSEQ * G4H;
    unsigned long long* stampBase = g_hstamp + (size_t)dir * 2 * HD;

    if (w == 0) {
        // ---------------- cell warp ----------------
        float creg = 0.0f;   // cell state for unit j0+lane (lanes 0..7)
        for (int s = 0; s < TSEQ; s++) {
            const int t   = dir ? (TSEQ - 1 - s) : s;
            const int par = s & 1;
            bar_sync(1 + par, SCAN_THREADS);   // parts + gin for step s ready

            float g = gin[par][lane];
#pragma unroll
            for (int p = 0; p < 8; p++) g += part[par][p][lane];
            float fg = __shfl_down_sync(0xffffffffu, g, 8);
            float gg = __shfl_down_sync(0xffffffffu, g, 16);
            float og = __shfl_down_sync(0xffffffffu, g, 24);
            if (lane < 8) {
                float c = sig_hw(fg) * creg + sig_hw(g) * tanh_hw(gg);
                creg = c;
                float h = sig_hw(og) * tanh_hw(c);
                // publish FIRST (unblocks all consumer CTAs), then persist
                unsigned long long pk =
                    ((unsigned long long)(unsigned)(s + 1) << 32) |
                    (unsigned long long)__float_as_uint(h);
                st_relaxed_u64(stampBase + (size_t)par * HD + j0 + lane, pk);
                hcat[(size_t)t * (2 * HD) + dir * HD + j0 + lane] = h;
            }
        }
    } else {
        // ---------------- producer warps ----------------
        const int seg = w - 1;               // k-segment 0..7
        const int row = lane;                // gate-row 0..31
        const int q = row >> 3, jj = row & 7;
        const int R = q * HD + j0 + jj;      // global gate row in [0,4H)

        // Whh slice in registers as packed pairs: 64 floats = 32 u64
        const ulonglong2* wsrc2 =
            (const ulonglong2*)(Whh + ((size_t)dir * G4H + R) * HD + seg * 64);
        ulonglong2 w2[16];
#pragma unroll
        for (int i = 0; i < 16; i++) w2[i] = wsrc2[i];

        // seg7 warp stages G rows (prefetch one step ahead)
        float gnext = 0.0f;
        if (seg == 7) {
            int t0 = dir ? (TSEQ - 1) : 0;
            gnext = __ldg(Gd + (size_t)t0 * G4H + R);
        }

        for (int s = 0; s < TSEQ; s++) {
            const int par = s & 1;

            // fill this warp's 64-float h segment
            if (s == 0) {
                hbuf[seg][lane * 2]     = 0.0f;
                hbuf[seg][lane * 2 + 1] = 0.0f;
            } else {
                const unsigned long long* src =
                    stampBase + ((size_t)((s + 1) & 1)) * HD + seg * 64 + lane * 2;
                const unsigned need = (unsigned)s;
                unsigned long long v0, v1;
                for (;;) {
                    v0 = ld_relaxed_u64(src);
                    v1 = ld_relaxed_u64(src + 1);
                    bool ok = ((unsigned)(v0 >> 32) >= need) &&
                              ((unsigned)(v1 >> 32) >= need);
                    if (__all_sync(0xffffffffu, ok)) break;
                }
                hbuf[seg][lane * 2]     = __uint_as_float((unsigned)v0);
                hbuf[seg][lane * 2 + 1] = __uint_as_float((unsigned)v1);
            }
            __syncwarp();

            // packed dot: 32 FFMA2 (64 MACs) registers x smem-broadcast h
            const ulonglong2* hb2 = (const ulonglong2*)hbuf[seg];
            unsigned long long a0 = 0ULL, a1 = 0ULL, a2 = 0ULL, a3 = 0ULL;
#pragma unroll
            for (int i = 0; i < 16; i += 2) {
                ulonglong2 h0 = hb2[i];
                ulonglong2 h1 = hb2[i + 1];
                a0 = ffma2(w2[i].x,     h0.x, a0);
                a1 = ffma2(w2[i].y,     h0.y, a1);
                a2 = ffma2(w2[i + 1].x, h1.x, a2);
                a3 = ffma2(w2[i + 1].y, h1.y, a3);
            }
            float2 f0 = unpack2(a0), f1 = unpack2(a1),
                   f2 = unpack2(a2), f3 = unpack2(a3);
            part[par][seg][row] =
                ((f0.x + f0.y) + (f1.x + f1.y)) + ((f2.x + f2.y) + (f3.x + f3.y));

            // seg7: stage this step's G, prefetch next
            if (seg == 7) {
                gin[par][row] = gnext;
                if (s + 1 < TSEQ) {
                    int tn = dir ? (TSEQ - 2 - s) : (s + 1);
                    gnext = __ldg(Gd + (size_t)tn * G4H + R);
                }
            }

            bar_arrive(1 + par, SCAN_THREADS);   // step-s inputs ready for cell warp
        }
    }
}

// ---------------------------------------------------------------------------
// 4) tag projection: feats[t][tag] = hcat1[t] . W_tag[tag] + b_tag[tag]
// ---------------------------------------------------------------------------
__global__ void feats_kernel(const float* __restrict__ Wtag,
                             const float* __restrict__ btag) {
    int t = blockIdx.x;
    __shared__ float xs[2 * HD];
    for (int i = threadIdx.x; i < 2 * HD; i += 192)
        xs[i] = g_hcat1[(size_t)t * (2 * HD) + i];
    __syncthreads();
    int tag = threadIdx.x / 16;
    int sg  = threadIdx.x % 16;
    const float* w = Wtag + (size_t)tag * (2 * HD) + sg * 64;
    const float* x = xs + sg * 64;
    float s = 0.0f;
#pragma unroll
    for (int i = 0; i < 64; i++) s = fmaf(w[i], x[i], s);
#pragma unroll
    for (int o = 8; o > 0; o >>= 1)
        s += __shfl_down_sync(0xffffffffu, s, o, 16);
    if (sg == 0) g_feats[t * NTAGS + tag] = s + btag[tag];
}

// ---------------------------------------------------------------------------
// 5) Viterbi + backtrace (single block; warp0 scans; feats staged in smem)
// ---------------------------------------------------------------------------
#define VIT_SMEM (TSEQ * NTAGS * 4 + TSEQ * NTAGS)

__global__ void viterbi_kernel(const float* __restrict__ trans,
                               float* __restrict__ out, int out_size) {
    extern __shared__ char vsm[];
    float* fsh = (float*)vsm;
    unsigned char* bp = (unsigned char*)(vsm + TSEQ * NTAGS * 4);

    for (int i = threadIdx.x; i < TSEQ * NTAGS; i += blockDim.x)
        fsh[i] = g_feats[i];
    __syncthreads();

    if (threadIdx.x >= 32) return;
    const int lane = threadIdx.x;

    float tr[NTAGS];
    if (lane < NTAGS) {
#pragma unroll
        for (int p = 0; p < NTAGS; p++) tr[p] = trans[lane * NTAGS + p];
    } else {
#pragma unroll
        for (int p = 0; p < NTAGS; p++) tr[p] = -3e38f;
    }

    float fv = (lane == START_TAG) ? 0.0f : ((lane < NTAGS) ? NEGV : -3e38f);
    float featp = (lane < NTAGS) ? fsh[lane] : 0.0f;

    for (int t = 0; t < TSEQ; t++) {
        float featn = (lane < NTAGS && t + 1 < TSEQ) ? fsh[(t + 1) * NTAGS + lane] : 0.0f;
        float best = -3e38f;
        int arg = 0;
#pragma unroll
        for (int p = 0; p < NTAGS; p++) {
            float fp = __shfl_sync(0xffffffffu, fv, p);
            float sc = fp + tr[p];
            if (sc > best) { best = sc; arg = p; }
        }
        if (lane < NTAGS) {
            bp[t * NTAGS + lane] = (unsigned char)arg;
            fv = best + featp;
        } else {
            fv = -3e38f;
        }
        featp = featn;
    }

    float term = (lane < NTAGS) ? fv + trans[STOP_TAG * NTAGS + lane] : -3e38f;
    float bs = term;
    int bi = lane;
#pragma unroll
    for (int o = 16; o > 0; o >>= 1) {
        float os = __shfl_down_sync(0xffffffffu, bs, o);
        int   oi = __shfl_down_sync(0xffffffffu, bi, o);
        if (os > bs || (os == bs && oi < bi)) { bs = os; bi = oi; }
    }
    __syncwarp();

    if (lane == 0) {
        float score = bs;
        int tag = bi;
        if (out_size >= TSEQ + 1) {
            out[0] = score;
            out[TSEQ] = (float)tag;
            for (int t = TSEQ - 1; t >= 1; t--) {
                tag = bp[t * NTAGS + tag];
                out[t] = (float)tag;
            }
            for (int i = TSEQ + 1; i < out_size; i++) out[i] = 0.0f;
        } else {
            int n = out_size;
            if (n > 0) {
                if (TSEQ - 1 < n) out[TSEQ - 1] = (float)tag;
                for (int t = TSEQ - 1; t >= 1; t--) {
                    tag = bp[t * NTAGS + tag];
                    if (t - 1 < n) out[t - 1] = (float)tag;
                }
            }
        }
    }
}

// ---------------------------------------------------------------------------
// launch
// ---------------------------------------------------------------------------
extern "C" void kernel_launch(void* const* d_in, const int* in_sizes, int n_in,
                              void* d_out, int out_size) {
    const int*   sentence = (const int*)  d_in[0];
    const float* emb      = (const float*)d_in[1];
    const float* Wih0     = (const float*)d_in[2];
    const float* Whh0     = (const float*)d_in[3];
    const float* bih0     = (const float*)d_in[4];
    const float* bhh0     = (const float*)d_in[5];
    const float* Wih1     = (const float*)d_in[6];
    const float* Whh1     = (const float*)d_in[7];
    const float* bih1     = (const float*)d_in[8];
    const float* bhh1     = (const float*)d_in[9];
    const float* Wtag     = (const float*)d_in[10];
    const float* btag     = (const float*)d_in[11];
    const float* trans    = (const float*)d_in[12];
    float* out = (float*)d_out;

    cudaFuncSetAttribute(viterbi_kernel,
                         cudaFuncAttributeMaxDynamicSharedMemorySize, VIT_SMEM);

    embed_kernel<<<TSEQ, 128>>>(sentence, emb);

    // ---- layer 0 ----
    init_stamps_kernel<<<4, 512>>>();
    gemm_bias_kernel<<<dim3(16, 16, 2), 256>>>(Wih0, bih0, bhh0, EMB, 0);
    scan_kernel<<<128, SCAN_THREADS>>>(Whh0, 0);

    // ---- layer 1 ----
    init_stamps_kernel<<<4, 512>>>();
    gemm_bias_kernel<<<dim3(16, 16, 2), 256>>>(Wih1, bih1, bhh1, 2 * HD, 1);
    scan_kernel<<<128, SCAN_THREADS>>>(Whh1, 1);

    // ---- CRF ----
    feats_kernel<<<TSEQ, 192>>>(Wtag, btag);
    viterbi_kernel<<<1, 128, VIT_SMEM>>>(trans, out, out_size);
}